// round 1
// baseline (speedup 1.0000x reference)
#include <cuda_runtime.h>
#include <cstdint>

#define THREADS   512
#define CTA_M     128
#define XST        68          // X chunk stride [128][64] (+4 pad, conflict-free frag loads)
#define WST       264          // W chunk stride [64][256] (+8 pad)
#define HST       260          // H stride [128][256] (+4 pad)
#define SH_FLOATS (128 * HST)  // 33280 floats
#define SW_FLOATS (64 * WST)   // 16896 floats
#define SMEM_BYTES ((SH_FLOATS + SW_FLOATS) * 4)  // 200704 B

__device__ __forceinline__ uint32_t f2tf32(float x) {
    uint32_t r;
    asm("cvt.rna.tf32.f32 %0, %1;" : "=r"(r) : "f"(x));
    return r;
}
__device__ __forceinline__ float f2tf32f(float x) { return __uint_as_float(f2tf32(x)); }

__device__ __forceinline__ void mma8(float* c,
                                     uint32_t a0, uint32_t a1, uint32_t a2, uint32_t a3,
                                     uint32_t b0, uint32_t b1) {
    asm volatile(
        "mma.sync.aligned.m16n8k8.row.col.f32.tf32.tf32.f32 "
        "{%0,%1,%2,%3}, {%4,%5,%6,%7}, {%8,%9}, {%0,%1,%2,%3};\n"
        : "+f"(c[0]), "+f"(c[1]), "+f"(c[2]), "+f"(c[3])
        : "r"(a0), "r"(a1), "r"(a2), "r"(a3), "r"(b0), "r"(b1));
}

__device__ __forceinline__ float softplus_f(float x) {
    // torch Softplus(beta=1, threshold=20)
    return (x > 20.0f) ? x : log1pf(expf(x));
}

// One 64-wide K-chunk of GEMM. A in smem (fp32 bits already tf32-rounded),
// W chunk in smem [64][NCOLS] at stride WST. Warp tile: 32 rows x (NT*8) cols.
template <int NT>
__device__ __forceinline__ void gemm_chunk(float acc[2][NT][4],
                                           const float* sA, int astr,
                                           const float* sW,
                                           int m0, int n0, int g, int t) {
#pragma unroll
    for (int kk = 0; kk < 64; kk += 8) {
        uint32_t a[2][4];
#pragma unroll
        for (int mt = 0; mt < 2; mt++) {
            const float* ap = sA + (m0 + mt * 16 + g) * astr + kk + t;
            a[mt][0] = __float_as_uint(ap[0]);
            a[mt][1] = __float_as_uint(ap[8 * astr]);
            a[mt][2] = __float_as_uint(ap[4]);
            a[mt][3] = __float_as_uint(ap[8 * astr + 4]);
        }
#pragma unroll
        for (int nt = 0; nt < NT; nt++) {
            const float* bp = sW + (kk + t) * WST + n0 + nt * 8 + g;
            uint32_t b0 = __float_as_uint(bp[0]);
            uint32_t b1 = __float_as_uint(bp[4 * WST]);
            mma8(acc[0][nt], a[0][0], a[0][1], a[0][2], a[0][3], b0, b1);
            mma8(acc[1][nt], a[1][0], a[1][1], a[1][2], a[1][3], b0, b1);
        }
    }
}

// Stage 64 rows x NCOLS of weights (rows kc*64..+64) into sW, tf32-rounded.
template <int NCOLS>
__device__ __forceinline__ void stage_w(float* sW, const float* __restrict__ Wg,
                                        int kc, int tid) {
    const int NF4 = NCOLS / 4;
    const int ITER = (64 * NF4) / THREADS;
#pragma unroll
    for (int it = 0; it < ITER; it++) {
        int i = tid + it * THREADS;
        int row = i / NF4;
        int c4 = i % NF4;
        float4 v = *(const float4*)(Wg + (long)(kc * 64 + row) * NCOLS + c4 * 4);
        float4 o;
        o.x = f2tf32f(v.x); o.y = f2tf32f(v.y);
        o.z = f2tf32f(v.z); o.w = f2tf32f(v.w);
        *(float4*)(sW + row * WST + c4 * 4) = o;
    }
}

// Stage X chunk kc (64 K-columns of the virtual concat) for 128 edges.
__device__ __forceinline__ void stage_x(float* sX, int kc, long e0,
                                        const float* __restrict__ src,
                                        const float* __restrict__ dstp,
                                        const float* __restrict__ ea,
                                        const float* __restrict__ u,
                                        const void* __restrict__ batch,
                                        int b64, int tid) {
    int seg = kc >> 1;
    int off = (kc & 1) * 64;
#pragma unroll
    for (int it = 0; it < 4; it++) {  // 128 rows * 16 float4 / 512 threads
        int i = tid + it * THREADS;
        int row = i >> 4;
        int c4 = i & 15;
        const float* base;
        long r;
        if (seg == 0)      { base = src;  r = e0 + row; }
        else if (seg == 1) { base = dstp; r = e0 + row; }
        else if (seg == 2) { base = ea;   r = e0 + row; }
        else {
            long bi = b64 ? (long)((const long long*)batch)[e0 + row]
                          : (long)((const int*)batch)[e0 + row];
            base = u; r = bi;
        }
        float4 v = *(const float4*)(base + r * 128 + off + c4 * 4);
        float4 o;
        o.x = f2tf32f(v.x); o.y = f2tf32f(v.y);
        o.z = f2tf32f(v.z); o.w = f2tf32f(v.w);
        *(float4*)(sX + row * XST + c4 * 4) = o;
    }
}

// bias + softplus + tf32-round, write to sH [128][256]@HST
__device__ __forceinline__ void epi_smem(float acc[2][8][4], float* sH,
                                         const float* __restrict__ bias,
                                         int m0, int n0, int g, int t) {
#pragma unroll
    for (int nt = 0; nt < 8; nt++) {
        int c = n0 + nt * 8 + 2 * t;
        float bb0 = bias[c];
        float bb1 = bias[c + 1];
#pragma unroll
        for (int mt = 0; mt < 2; mt++) {
            int r = m0 + mt * 16 + g;
            sH[r * HST + c]           = f2tf32f(softplus_f(acc[mt][nt][0] + bb0));
            sH[r * HST + c + 1]       = f2tf32f(softplus_f(acc[mt][nt][1] + bb1));
            sH[(r + 8) * HST + c]     = f2tf32f(softplus_f(acc[mt][nt][2] + bb0));
            sH[(r + 8) * HST + c + 1] = f2tf32f(softplus_f(acc[mt][nt][3] + bb1));
        }
    }
}

__global__ void __launch_bounds__(THREADS, 1)
edge_mlp_kernel(const float* __restrict__ src, const float* __restrict__ dstp,
                const float* __restrict__ ea, const float* __restrict__ u,
                const void* __restrict__ batch,
                const float* __restrict__ W1, const float* __restrict__ b1,
                const float* __restrict__ W2, const float* __restrict__ b2,
                const float* __restrict__ W3, const float* __restrict__ b3,
                float* __restrict__ out) {
    extern __shared__ float smem[];
    float* sH = smem;              // [128][HST]; X chunk aliases front of this
    float* sW = smem + SH_FLOATS;  // [64][WST]
    float* sX = smem;

    int tid = threadIdx.x;
    int wid = tid >> 5;
    int lane = tid & 31;
    int g = lane >> 2;   // 0..7
    int t = lane & 3;    // 0..3
    int warp_m = wid & 3;       // 4 warps over M
    int warp_n = wid >> 2;      // 4 warps over N
    int m0 = warp_m * 32;
    int n0 = warp_n * 64;       // layers 1/2 (N=256)
    long e0 = (long)blockIdx.x * CTA_M;

    // Detect batch dtype (int64 vs silently-downcast int32): int32 pairs read
    // as int64 would be >= 2^32 with prob 63/64 per sample.
    __shared__ int b64s;
    if (tid == 0) {
        const long long* p = (const long long*)batch;
        int f = 1;
        for (int i = 0; i < 16; i++) {
            long long v = p[i];
            if (v < 0 || v >= 64) f = 0;
        }
        b64s = f;
    }
    __syncthreads();
    int b64 = b64s;

    float acc[2][8][4];
#pragma unroll
    for (int a = 0; a < 2; a++)
#pragma unroll
        for (int b = 0; b < 8; b++)
#pragma unroll
            for (int cc = 0; cc < 4; cc++) acc[a][b][cc] = 0.0f;

    // ---------------- Layer 1: [128x512] @ [512x256] ----------------
    for (int kc = 0; kc < 8; kc++) {
        __syncthreads();  // previous chunk consumers done before overwrite
        stage_x(sX, kc, e0, src, dstp, ea, u, batch, b64, tid);
        stage_w<256>(sW, W1, kc, tid);
        __syncthreads();
        gemm_chunk<8>(acc, sX, XST, sW, m0, n0, g, t);
    }
    __syncthreads();
    epi_smem(acc, sH, b1, m0, n0, g, t);  // H1 (tf32-rounded) into sH

    // ---------------- Layer 2: [128x256] @ [256x256] ----------------
#pragma unroll
    for (int a = 0; a < 2; a++)
#pragma unroll
        for (int b = 0; b < 8; b++)
#pragma unroll
            for (int cc = 0; cc < 4; cc++) acc[a][b][cc] = 0.0f;

    for (int kc = 0; kc < 4; kc++) {
        stage_w<256>(sW, W2, kc, tid);
        __syncthreads();  // H writes + W stage visible
        gemm_chunk<8>(acc, sH + kc * 64, HST, sW, m0, n0, g, t);
        __syncthreads();  // all reads of sW done before next stage
    }
    epi_smem(acc, sH, b2, m0, n0, g, t);  // H2 overwrites H1 (reads all done)

    // ---------------- Layer 3: [128x256] @ [256x128] ----------------
    float acc3[2][4][4];
#pragma unroll
    for (int a = 0; a < 2; a++)
#pragma unroll
        for (int b = 0; b < 4; b++)
#pragma unroll
            for (int cc = 0; cc < 4; cc++) acc3[a][b][cc] = 0.0f;

    int n0_3 = warp_n * 32;  // N=128 over 4 warps
    for (int kc = 0; kc < 4; kc++) {
        stage_w<128>(sW, W3, kc, tid);
        __syncthreads();
        gemm_chunk<4>(acc3, sH + kc * 64, HST, sW, m0, n0_3, g, t);
        __syncthreads();
    }

    // epilogue: + b3, write out [E][128]
#pragma unroll
    for (int nt = 0; nt < 4; nt++) {
        int c = n0_3 + nt * 8 + 2 * t;
        float bb0 = b3[c];
        float bb1 = b3[c + 1];
#pragma unroll
        for (int mt = 0; mt < 2; mt++) {
            long r = e0 + m0 + mt * 16 + g;
            float2 v0 = make_float2(acc3[mt][nt][0] + bb0, acc3[mt][nt][1] + bb1);
            float2 v1 = make_float2(acc3[mt][nt][2] + bb0, acc3[mt][nt][3] + bb1);
            *(float2*)(out + r * 128 + c) = v0;
            *(float2*)(out + (r + 8) * 128 + c) = v1;
        }
    }
}

extern "C" void kernel_launch(void* const* d_in, const int* in_sizes, int n_in,
                              void* d_out, int out_size) {
    const float* src  = (const float*)d_in[0];
    const float* dstp = (const float*)d_in[1];
    const float* ea   = (const float*)d_in[2];
    const float* u    = (const float*)d_in[3];
    const void*  bat  = (const void*)d_in[4];   // int64 or int32, detected in-kernel
    const float* W1   = (const float*)d_in[5];
    const float* b1   = (const float*)d_in[6];
    const float* W2   = (const float*)d_in[7];
    const float* b2   = (const float*)d_in[8];
    const float* W3   = (const float*)d_in[9];
    const float* b3   = (const float*)d_in[10];
    float* out = (float*)d_out;

    cudaFuncSetAttribute(edge_mlp_kernel,
                         cudaFuncAttributeMaxDynamicSharedMemorySize, SMEM_BYTES);

    const int n_edges = in_sizes[4];          // batch has one entry per edge
    const int grid = n_edges / CTA_M;         // 400000 / 128 = 3125 exactly
    edge_mlp_kernel<<<grid, THREADS, SMEM_BYTES>>>(src, dstp, ea, u, bat,
                                                   W1, b1, W2, b2, W3, b3, out);
}

// round 3
// speedup vs baseline: 1.0123x; 1.0123x over previous
#include <cuda_runtime.h>
#include <cstdint>

#define THREADS 512
#define CTA_M   128
#define HST     260                    // H row stride (floats), pad-4 conflict-free
#define SXOFF   (128 * HST)            // 33280
#define SXSZ    (128 * 32)             // 4096 floats per X buffer
#define SWOFF   (SXOFF + 2 * SXSZ)     // 41472
#define SWSZ    (32 * 256)             // 8192 floats per W buffer
#define SMEM_FLOATS (SWOFF + 2 * SWSZ) // 57856
#define SMEM_BYTES  (SMEM_FLOATS * 4)  // 231424 <= 232448

__device__ __forceinline__ float f2tf32f(float x) {
    uint32_t r; asm("cvt.rna.tf32.f32 %0, %1;" : "=r"(r) : "f"(x));
    return __uint_as_float(r);
}
__device__ __forceinline__ float softplus_f(float x) {
    // torch Softplus(beta=1, threshold=20); fast-math exp/log (err ~1e-7 abs, << tf32 noise)
    return (x > 20.0f) ? x : __logf(1.0f + __expf(x));
}
__device__ __forceinline__ void mma8(float* c,
                                     uint32_t a0, uint32_t a1, uint32_t a2, uint32_t a3,
                                     uint32_t b0, uint32_t b1) {
    asm volatile(
        "mma.sync.aligned.m16n8k8.row.col.f32.tf32.tf32.f32 "
        "{%0,%1,%2,%3}, {%4,%5,%6,%7}, {%8,%9}, {%0,%1,%2,%3};\n"
        : "+f"(c[0]), "+f"(c[1]), "+f"(c[2]), "+f"(c[3])
        : "r"(a0), "r"(a1), "r"(a2), "r"(a3), "r"(b0), "r"(b1));
}

// ---- GEMM on one 32-wide K chunk.
// AX=true: A from swizzled X buffer (stride 32, col c -> c ^ ((row&7)<<2))
// AX=false: A from H (stride HST, plain, caller passes sA = sH + chunk_col)
// B from swizzled W buffer (stride 256, col n -> n ^ ((k&7)<<3))
template <int NT, bool AX>
__device__ __forceinline__ void gemm32(float acc[2][NT][4],
                                       const float* sA, const float* sB,
                                       int m0, int n0, int g, int t) {
#pragma unroll
    for (int kk = 0; kk < 32; kk += 8) {
        uint32_t a[2][4];
#pragma unroll
        for (int mt = 0; mt < 2; mt++) {
            int r = m0 + mt * 16 + g;
            if (AX) {
                const float* p = sA + r * 32;
                int c0 = (kk + t) ^ (g << 2);
                int c1 = (kk + t + 4) ^ (g << 2);
                a[mt][0] = __float_as_uint(p[c0]);
                a[mt][1] = __float_as_uint(p[8 * 32 + c0]);
                a[mt][2] = __float_as_uint(p[c1]);
                a[mt][3] = __float_as_uint(p[8 * 32 + c1]);
            } else {
                const float* p = sA + r * HST + kk + t;
                a[mt][0] = __float_as_uint(p[0]);
                a[mt][1] = __float_as_uint(p[8 * HST]);
                a[mt][2] = __float_as_uint(p[4]);
                a[mt][3] = __float_as_uint(p[8 * HST + 4]);
            }
        }
        const float* pb0 = sB + (kk + t) * 256;
        const float* pb1 = sB + (kk + t + 4) * 256;
        int x0 = t << 3;
        int x1 = (t + 4) << 3;
#pragma unroll
        for (int nt = 0; nt < NT; nt++) {
            int n = n0 + nt * 8 + g;
            uint32_t b0 = __float_as_uint(pb0[n ^ x0]);
            uint32_t b1 = __float_as_uint(pb1[n ^ x1]);
            mma8(acc[0][nt], a[0][0], a[0][1], a[0][2], a[0][3], b0, b1);
            mma8(acc[1][nt], a[1][0], a[1][1], a[1][2], a[1][3], b0, b1);
        }
    }
}

// ---- X staging: LDG phase (to regs) and STS phase (cvt + swizzled store) ----
__device__ __forceinline__ void x_ldg(float4 v[2], int kc, long e0,
                                      const float* __restrict__ src,
                                      const float* __restrict__ dstp,
                                      const float* __restrict__ ea,
                                      const float* __restrict__ u,
                                      const void* __restrict__ batch, int b64, int tid) {
    int k0 = kc * 32, seg = k0 >> 7, off = k0 & 127;
#pragma unroll
    for (int it = 0; it < 2; it++) {
        int task = tid + it * THREADS;
        int row = task >> 3, q = task & 7;
        const float* p;
        if (seg == 0)      p = src  + (e0 + row) * 128;
        else if (seg == 1) p = dstp + (e0 + row) * 128;
        else if (seg == 2) p = ea   + (e0 + row) * 128;
        else {
            long bi = b64 ? (long)((const long long*)batch)[e0 + row]
                          : (long)((const int*)batch)[e0 + row];
            p = u + bi * 128;
        }
        v[it] = *(const float4*)(p + off + q * 4);
    }
}
__device__ __forceinline__ void x_sts(float* sx, const float4 v[2], int tid) {
#pragma unroll
    for (int it = 0; it < 2; it++) {
        int task = tid + it * THREADS;
        int row = task >> 3, q = task & 7;
        float4 o;
        o.x = f2tf32f(v[it].x); o.y = f2tf32f(v[it].y);
        o.z = f2tf32f(v[it].z); o.w = f2tf32f(v[it].w);
        int c = (q * 4) ^ ((row & 7) << 2);
        *(float4*)(sx + row * 32 + c) = o;
    }
}

// ---- W staging (rows kc*32..+32 of [K][N] weight), swizzled stride-256 store ----
template <int N>
__device__ __forceinline__ void w_ldg(float4* v, const float* __restrict__ Wg,
                                      int kc, int tid) {
    const int F4 = N / 4, IT = N / 64;
#pragma unroll
    for (int it = 0; it < IT; it++) {
        int task = tid + it * THREADS;
        int row = task / F4, c4 = task % F4;
        v[it] = *(const float4*)(Wg + (long)(kc * 32 + row) * N + c4 * 4);
    }
}
template <int N>
__device__ __forceinline__ void w_sts(float* sw, const float4* v, int tid) {
    const int F4 = N / 4, IT = N / 64;
#pragma unroll
    for (int it = 0; it < IT; it++) {
        int task = tid + it * THREADS;
        int row = task / F4, c4 = task % F4;
        float4 o;
        o.x = f2tf32f(v[it].x); o.y = f2tf32f(v[it].y);
        o.z = f2tf32f(v[it].z); o.w = f2tf32f(v[it].w);
        int n = (c4 * 4) ^ ((row & 7) << 3);
        *(float4*)(sw + row * 256 + n) = o;
    }
}

// ---- epilogue for layers 1/2: bias + softplus + tf32-round -> sH ----
__device__ __forceinline__ void epi_h(float acc[2][8][4], float* sH,
                                      const float* __restrict__ bias,
                                      int m0, int n0, int g, int t) {
#pragma unroll
    for (int nt = 0; nt < 8; nt++) {
        int c = n0 + nt * 8 + 2 * t;
        float bb0 = __ldg(bias + c);
        float bb1 = __ldg(bias + c + 1);
#pragma unroll
        for (int mt = 0; mt < 2; mt++) {
            int r = m0 + mt * 16 + g;
            sH[r * HST + c]           = f2tf32f(softplus_f(acc[mt][nt][0] + bb0));
            sH[r * HST + c + 1]       = f2tf32f(softplus_f(acc[mt][nt][1] + bb1));
            sH[(r + 8) * HST + c]     = f2tf32f(softplus_f(acc[mt][nt][2] + bb0));
            sH[(r + 8) * HST + c + 1] = f2tf32f(softplus_f(acc[mt][nt][3] + bb1));
        }
    }
}

__global__ void __launch_bounds__(THREADS, 1)
edge_mlp_pipe(const float* __restrict__ src, const float* __restrict__ dstp,
              const float* __restrict__ ea, const float* __restrict__ u,
              const void* __restrict__ batch,
              const float* __restrict__ W1, const float* __restrict__ b1,
              const float* __restrict__ W2, const float* __restrict__ b2,
              const float* __restrict__ W3, const float* __restrict__ b3,
              float* __restrict__ out) {
    extern __shared__ float sm[];
    float* sH = sm;
    float* sX = sm + SXOFF;
    float* sW = sm + SWOFF;

    int tid = threadIdx.x;
    int wid = tid >> 5;
    int lane = tid & 31;
    int g = lane >> 2;
    int t = lane & 3;
    int m0 = (wid & 3) * 32;
    int n0 = (wid >> 2) * 64;   // layers 1/2
    int n3 = (wid >> 2) * 32;   // layer 3
    long e0 = (long)blockIdx.x * CTA_M;

    __shared__ int b64s;
    if (tid == 0) {
        const long long* p = (const long long*)batch;
        int f = 1;
        for (int i = 0; i < 16; i++) { long long v = p[i]; if (v < 0 || v >= 64) f = 0; }
        b64s = f;
    }
    __syncthreads();
    int b64 = b64s;

    float acc[2][8][4];
#pragma unroll
    for (int a = 0; a < 2; a++)
#pragma unroll
        for (int b = 0; b < 8; b++)
#pragma unroll
            for (int c = 0; c < 4; c++) acc[a][b][c] = 0.0f;

    // ================= Layer 1: K=512 (16 chunks), N=256 =================
    {
        float4 xv[2];
        float4 wv[4];
        x_ldg(xv, 0, e0, src, dstp, ea, u, batch, b64, tid);
        w_ldg<256>(wv, W1, 0, tid);
        x_sts(sX, xv, tid);
        w_sts<256>(sW, wv, tid);
        __syncthreads();
#pragma unroll 1
        for (int kc = 0; kc < 16; kc++) {
            int cur = kc & 1, nxt = cur ^ 1;
            bool pf = (kc + 1 < 16);
            if (pf) {
                x_ldg(xv, kc + 1, e0, src, dstp, ea, u, batch, b64, tid);
                w_ldg<256>(wv, W1, kc + 1, tid);
            }
            gemm32<8, true>(acc, sX + cur * SXSZ, sW + cur * SWSZ, m0, n0, g, t);
            if (pf) {
                x_sts(sX + nxt * SXSZ, xv, tid);
                w_sts<256>(sW + nxt * SWSZ, wv, tid);
            }
            __syncthreads();
        }
    }
    epi_h(acc, sH, b1, m0, n0, g, t);

    // ================= Layer 2: K=256 (8 chunks), N=256, A = sH ==========
    {
        float4 wv[4];
        w_ldg<256>(wv, W2, 0, tid);
        w_sts<256>(sW, wv, tid);
        __syncthreads();   // H writes + W chunk0 visible
#pragma unroll
        for (int a = 0; a < 2; a++)
#pragma unroll
            for (int b = 0; b < 8; b++)
#pragma unroll
                for (int c = 0; c < 4; c++) acc[a][b][c] = 0.0f;
#pragma unroll 1
        for (int kc = 0; kc < 8; kc++) {
            int cur = kc & 1, nxt = cur ^ 1;
            bool pf = (kc + 1 < 8);
            if (pf) w_ldg<256>(wv, W2, kc + 1, tid);
            gemm32<8, false>(acc, sH + kc * 32, sW + cur * SWSZ, m0, n0, g, t);
            if (pf) w_sts<256>(sW + nxt * SWSZ, wv, tid);
            __syncthreads();
        }
    }
    epi_h(acc, sH, b2, m0, n0, g, t);

    // ================= Layer 3: K=256 (8 chunks), N=128, A = sH ==========
    float acc3[2][4][4];
#pragma unroll
    for (int a = 0; a < 2; a++)
#pragma unroll
        for (int b = 0; b < 4; b++)
#pragma unroll
            for (int c = 0; c < 4; c++) acc3[a][b][c] = 0.0f;
    {
        float4 wv[2];
        w_ldg<128>(wv, W3, 0, tid);
        w_sts<128>(sW, wv, tid);
        __syncthreads();
#pragma unroll 1
        for (int kc = 0; kc < 8; kc++) {
            int cur = kc & 1, nxt = cur ^ 1;
            bool pf = (kc + 1 < 8);
            if (pf) w_ldg<128>(wv, W3, kc + 1, tid);
            gemm32<4, false>(acc3, sH + kc * 32, sW + cur * SWSZ, m0, n3, g, t);
            if (pf) w_sts<128>(sW + nxt * SWSZ, wv, tid);
            __syncthreads();
        }
    }

    // ---- output epilogue: bias -> sH bounce (cols 0..127) -> coalesced STG
#pragma unroll
    for (int nt = 0; nt < 4; nt++) {
        int c = n3 + nt * 8 + 2 * t;
        float bb0 = __ldg(b3 + c);
        float bb1 = __ldg(b3 + c + 1);
#pragma unroll
        for (int mt = 0; mt < 2; mt++) {
            int r = m0 + mt * 16 + g;
            sH[r * HST + c]           = acc3[mt][nt][0] + bb0;
            sH[r * HST + c + 1]       = acc3[mt][nt][1] + bb1;
            sH[(r + 8) * HST + c]     = acc3[mt][nt][2] + bb0;
            sH[(r + 8) * HST + c + 1] = acc3[mt][nt][3] + bb1;
        }
    }
    __syncthreads();
#pragma unroll
    for (int it = 0; it < 8; it++) {
        int task = tid + it * THREADS;
        int row = task >> 5, c4 = task & 31;
        *(float4*)(out + (e0 + row) * 128 + c4 * 4) =
            *(const float4*)(sH + row * HST + c4 * 4);
    }
}

extern "C" void kernel_launch(void* const* d_in, const int* in_sizes, int n_in,
                              void* d_out, int out_size) {
    const float* src  = (const float*)d_in[0];
    const float* dstp = (const float*)d_in[1];
    const float* ea   = (const float*)d_in[2];
    const float* u    = (const float*)d_in[3];
    const void*  bat  = (const void*)d_in[4];
    const float* W1   = (const float*)d_in[5];
    const float* b1   = (const float*)d_in[6];
    const float* W2   = (const float*)d_in[7];
    const float* b2   = (const float*)d_in[8];
    const float* W3   = (const float*)d_in[9];
    const float* b3   = (const float*)d_in[10];
    float* out = (float*)d_out;

    cudaFuncSetAttribute(edge_mlp_pipe,
                         cudaFuncAttributeMaxDynamicSharedMemorySize, SMEM_BYTES);

    const int n_edges = in_sizes[4];
    const int grid = n_edges / CTA_M;   // 3125
    edge_mlp_pipe<<<grid, THREADS, SMEM_BYTES>>>(src, dstp, ea, u, bat,
                                                 W1, b1, W2, b2, W3, b3, out);
}

// round 4
// speedup vs baseline: 1.0319x; 1.0193x over previous
#include <cuda_runtime.h>
#include <cstdint>

#define THREADS 256
#define CTA_M   128
#define HST     260                       // H row stride (floats)
#define SXOFF   (128 * HST)               // 33280
#define SXSZ    (128 * 32)                // 4096 floats per X slot
#define SWOFF   (SXOFF + 2 * SXSZ)        // 41472
#define SWSZ    (32 * 256)                // 8192 floats per W slot
#define SMEM_FLOATS (SWOFF + 2 * SWSZ)    // 57856
#define SMEM_BYTES  (SMEM_FLOATS * 4)     // 231424

__device__ __forceinline__ uint32_t smem_u32(const void* p) {
    uint32_t a;
    asm("{ .reg .u64 t; cvta.to.shared.u64 t, %1; cvt.u32.u64 %0, t; }" : "=r"(a) : "l"(p));
    return a;
}
__device__ __forceinline__ float f2tf32f(float x) {
    uint32_t r; asm("cvt.rna.tf32.f32 %0, %1;" : "=r"(r) : "f"(x));
    return __uint_as_float(r);
}
__device__ __forceinline__ uint32_t tf32_bits(float x) {
    uint32_t r; asm("cvt.rna.tf32.f32 %0, %1;" : "=r"(r) : "f"(x));
    return r;
}
__device__ __forceinline__ float softplus_f(float x) {
    return (x > 20.0f) ? x : __logf(1.0f + __expf(x));
}
__device__ __forceinline__ void mma8(float* c,
                                     uint32_t a0, uint32_t a1, uint32_t a2, uint32_t a3,
                                     uint32_t b0, uint32_t b1) {
    asm volatile(
        "mma.sync.aligned.m16n8k8.row.col.f32.tf32.tf32.f32 "
        "{%0,%1,%2,%3}, {%4,%5,%6,%7}, {%8,%9}, {%0,%1,%2,%3};\n"
        : "+f"(c[0]), "+f"(c[1]), "+f"(c[2]), "+f"(c[3])
        : "r"(a0), "r"(a1), "r"(a2), "r"(a3), "r"(b0), "r"(b1));
}
__device__ __forceinline__ void cp16(uint32_t dst, const void* src) {
    asm volatile("cp.async.cg.shared.global [%0], [%1], 16;" :: "r"(dst), "l"(src) : "memory");
}
#define CP_COMMIT() asm volatile("cp.async.commit_group;" ::: "memory")
#define CP_WAIT1()  asm volatile("cp.async.wait_group 1;" ::: "memory")

// ---- GEMM on one 32-wide K chunk. Warp tile 64M x (NT*8)N, MT=4.
// AX: A from X buffer (stride 32, col c -> c ^ (g<<2), raw fp32 -> cvt)
// !AX: A from H (stride HST, pre-rounded tf32, no cvt)
// B from W buffer (stride 256, col n -> n ^ ((k&7)<<3)), CVTB selects raw/pre-rounded.
template <int NT, bool AX, bool CVTB>
__device__ __forceinline__ void gemm32(float acc[4][NT][4],
                                       const float* sA, const float* sB,
                                       int m0, int n0, int g, int t) {
#pragma unroll
    for (int kk = 0; kk < 32; kk += 8) {
        uint32_t a[4][4];
#pragma unroll
        for (int mt = 0; mt < 4; mt++) {
            int r = m0 + mt * 16 + g;
            if (AX) {
                const float* p = sA + r * 32;
                int c0 = (kk + t) ^ (g << 2);
                int c1 = (kk + t + 4) ^ (g << 2);
                a[mt][0] = tf32_bits(p[c0]);
                a[mt][1] = tf32_bits(p[8 * 32 + c0]);
                a[mt][2] = tf32_bits(p[c1]);
                a[mt][3] = tf32_bits(p[8 * 32 + c1]);
            } else {
                const float* p = sA + r * HST + kk + t;
                a[mt][0] = __float_as_uint(p[0]);
                a[mt][1] = __float_as_uint(p[8 * HST]);
                a[mt][2] = __float_as_uint(p[4]);
                a[mt][3] = __float_as_uint(p[8 * HST + 4]);
            }
        }
        const float* pb0 = sB + (kk + t) * 256;
        const float* pb1 = sB + (kk + t + 4) * 256;
        int x0 = t << 3;
        int x1 = (t + 4) << 3;
#pragma unroll
        for (int nt = 0; nt < NT; nt++) {
            int n = n0 + nt * 8 + g;
            uint32_t b0, b1;
            if (CVTB) {
                b0 = tf32_bits(pb0[n ^ x0]);
                b1 = tf32_bits(pb1[n ^ x1]);
            } else {
                b0 = __float_as_uint(pb0[n ^ x0]);
                b1 = __float_as_uint(pb1[n ^ x1]);
            }
#pragma unroll
            for (int mt = 0; mt < 4; mt++)
                mma8(acc[mt][nt], a[mt][0], a[mt][1], a[mt][2], a[mt][3], b0, b1);
        }
    }
}

// ---- async staging: X chunk kc (32 K-cols of concat) -> slot (raw fp32) ----
__device__ __forceinline__ void stage_x(uint32_t xbase, int kc, long e0,
                                        const float* __restrict__ src,
                                        const float* __restrict__ dstp,
                                        const float* __restrict__ ea,
                                        const float* __restrict__ u,
                                        const void* __restrict__ batch, int b64, int tid) {
    int k0 = kc * 32, seg = k0 >> 7, off = k0 & 127;
#pragma unroll
    for (int it = 0; it < 4; it++) {
        int task = tid + it * THREADS;
        int row = task >> 3, q = task & 7;
        const float* p;
        if (seg == 0)      p = src  + (e0 + row) * 128;
        else if (seg == 1) p = dstp + (e0 + row) * 128;
        else if (seg == 2) p = ea   + (e0 + row) * 128;
        else {
            long bi = b64 ? (long)((const long long*)batch)[e0 + row]
                          : (long)((const int*)batch)[e0 + row];
            p = u + bi * 128;
        }
        uint32_t dst = xbase + (row * 32 + ((q * 4) ^ ((row & 7) << 2))) * 4;
        cp16(dst, p + off + q * 4);
    }
}

// ---- async staging: W chunk kc (rows kc*32..+32 of [K][N]) -> slot ----
template <int N>
__device__ __forceinline__ void stage_w(uint32_t wbase, const float* __restrict__ Wg,
                                        int kc, int tid) {
    const int F4 = N / 4;
#pragma unroll
    for (int it = 0; it < (32 * F4) / THREADS; it++) {
        int task = tid + it * THREADS;
        int row = task / F4, c4 = task % F4;
        uint32_t dst = wbase + (row * 256 + ((c4 * 4) ^ ((row & 7) << 3))) * 4;
        cp16(dst, Wg + (long)(kc * 32 + row) * N + c4 * 4);
    }
}

// ---- epilogue layers 1/2: bias + softplus + tf32-round -> sH ----
template <int NT>
__device__ __forceinline__ void epi_h(float acc[4][NT][4], float* sH,
                                      const float* __restrict__ bias,
                                      int m0, int n0, int g, int t) {
#pragma unroll
    for (int nt = 0; nt < NT; nt++) {
        int c = n0 + nt * 8 + 2 * t;
        float bb0 = __ldg(bias + c);
        float bb1 = __ldg(bias + c + 1);
#pragma unroll
        for (int mt = 0; mt < 4; mt++) {
            int r = m0 + mt * 16 + g;
            sH[r * HST + c]           = f2tf32f(softplus_f(acc[mt][nt][0] + bb0));
            sH[r * HST + c + 1]       = f2tf32f(softplus_f(acc[mt][nt][1] + bb1));
            sH[(r + 8) * HST + c]     = f2tf32f(softplus_f(acc[mt][nt][2] + bb0));
            sH[(r + 8) * HST + c + 1] = f2tf32f(softplus_f(acc[mt][nt][3] + bb1));
        }
    }
}

__global__ void __launch_bounds__(THREADS, 1)
edge_mlp_v4(const float* __restrict__ src, const float* __restrict__ dstp,
            const float* __restrict__ ea, const float* __restrict__ u,
            const void* __restrict__ batch,
            const float* __restrict__ W1, const float* __restrict__ b1,
            const float* __restrict__ W2, const float* __restrict__ b2,
            const float* __restrict__ W3, const float* __restrict__ b3,
            float* __restrict__ out) {
    extern __shared__ float sm[];
    float* sH = sm;
    float* sX = sm + SXOFF;
    float* sW = sm + SWOFF;
    uint32_t sb = smem_u32(sm);
    uint32_t xb[2] = { sb + SXOFF * 4, sb + (SXOFF + SXSZ) * 4 };
    uint32_t wb[2] = { sb + SWOFF * 4, sb + (SWOFF + SWSZ) * 4 };

    int tid = threadIdx.x;
    int wid = tid >> 5;
    int lane = tid & 31;
    int g = lane >> 2;
    int t = lane & 3;
    int m0 = (wid & 1) * 64;       // 2 warps over M
    int n0 = (wid >> 1) * 64;      // 4 warps over N (layers 1/2)
    int n3 = (wid >> 1) * 32;      // layer 3
    long e0 = (long)blockIdx.x * CTA_M;

    __shared__ int b64s;
    if (tid == 0) {
        const long long* p = (const long long*)batch;
        int f = 1;
        for (int i = 0; i < 16; i++) { long long v = p[i]; if (v < 0 || v >= 64) f = 0; }
        b64s = f;
    }
    __syncthreads();
    int b64 = b64s;

    float acc[4][8][4];
#pragma unroll
    for (int a = 0; a < 4; a++)
#pragma unroll
        for (int b = 0; b < 8; b++)
#pragma unroll
            for (int c = 0; c < 4; c++) acc[a][b][c] = 0.0f;

    // ================= Layer 1: K=512 (16 chunks), N=256 =================
    stage_x(xb[0], 0, e0, src, dstp, ea, u, batch, b64, tid);
    stage_w<256>(wb[0], W1, 0, tid);
    CP_COMMIT();
    stage_x(xb[1], 1, e0, src, dstp, ea, u, batch, b64, tid);
    stage_w<256>(wb[1], W1, 1, tid);
    CP_COMMIT();
#pragma unroll 1
    for (int kc = 0; kc < 16; kc++) {
        int s = kc & 1;
        CP_WAIT1();
        __syncthreads();
        gemm32<8, true, true>(acc, sX + s * SXSZ, sW + s * SWSZ, m0, n0, g, t);
        __syncthreads();
        if (kc < 14) {
            stage_x(xb[s], kc + 2, e0, src, dstp, ea, u, batch, b64, tid);
            stage_w<256>(wb[s], W1, kc + 2, tid);
        }
        CP_COMMIT();
    }

    // ================= Layer 2: K=256 (8 chunks), N=256, A = sH ==========
    stage_w<256>(wb[0], W2, 0, tid); CP_COMMIT();
    stage_w<256>(wb[1], W2, 1, tid); CP_COMMIT();
    epi_h<8>(acc, sH, b1, m0, n0, g, t);
#pragma unroll
    for (int a = 0; a < 4; a++)
#pragma unroll
        for (int b = 0; b < 8; b++)
#pragma unroll
            for (int c = 0; c < 4; c++) acc[a][b][c] = 0.0f;
#pragma unroll 1
    for (int kc = 0; kc < 8; kc++) {
        int s = kc & 1;
        CP_WAIT1();
        __syncthreads();            // first iter also publishes sH
        gemm32<8, false, true>(acc, sH + kc * 32, sW + s * SWSZ, m0, n0, g, t);
        __syncthreads();
        if (kc < 6) stage_w<256>(wb[s], W2, kc + 2, tid);
        CP_COMMIT();
    }

    // ================= Layer 3: K=256 (8 chunks), N=128, A = sH ==========
    stage_w<128>(wb[0], W3, 0, tid); CP_COMMIT();
    stage_w<128>(wb[1], W3, 1, tid); CP_COMMIT();
    epi_h<8>(acc, sH, b2, m0, n0, g, t);
    float acc3[4][4][4];
#pragma unroll
    for (int a = 0; a < 4; a++)
#pragma unroll
        for (int b = 0; b < 4; b++)
#pragma unroll
            for (int c = 0; c < 4; c++) acc3[a][b][c] = 0.0f;
#pragma unroll 1
    for (int kc = 0; kc < 8; kc++) {
        int s = kc & 1;
        CP_WAIT1();
        __syncthreads();
        gemm32<4, false, true>(acc3, sH + kc * 32, sW + s * SWSZ, m0, n3, g, t);
        __syncthreads();
        if (kc < 6) stage_w<128>(wb[s], W3, kc + 2, tid);
        CP_COMMIT();
    }

    // ---- output epilogue: bias -> sH bounce (cols 0..127) -> coalesced STG
#pragma unroll
    for (int nt = 0; nt < 4; nt++) {
        int c = n3 + nt * 8 + 2 * t;
        float bb0 = __ldg(b3 + c);
        float bb1 = __ldg(b3 + c + 1);
#pragma unroll
        for (int mt = 0; mt < 4; mt++) {
            int r = m0 + mt * 16 + g;
            sH[r * HST + c]           = acc3[mt][nt][0] + bb0;
            sH[r * HST + c + 1]       = acc3[mt][nt][1] + bb1;
            sH[(r + 8) * HST + c]     = acc3[mt][nt][2] + bb0;
            sH[(r + 8) * HST + c + 1] = acc3[mt][nt][3] + bb1;
        }
    }
    __syncthreads();
#pragma unroll
    for (int it = 0; it < 16; it++) {
        int task = tid + it * THREADS;
        int row = task >> 5, c4 = task & 31;
        *(float4*)(out + (e0 + row) * 128 + c4 * 4) =
            *(const float4*)(sH + row * HST + c4 * 4);
    }
}

extern "C" void kernel_launch(void* const* d_in, const int* in_sizes, int n_in,
                              void* d_out, int out_size) {
    const float* src  = (const float*)d_in[0];
    const float* dstp = (const float*)d_in[1];
    const float* ea   = (const float*)d_in[2];
    const float* u    = (const float*)d_in[3];
    const void*  bat  = (const void*)d_in[4];
    const float* W1   = (const float*)d_in[5];
    const float* b1   = (const float*)d_in[6];
    const float* W2   = (const float*)d_in[7];
    const float* b2   = (const float*)d_in[8];
    const float* W3   = (const float*)d_in[9];
    const float* b3   = (const float*)d_in[10];
    float* out = (float*)d_out;

    cudaFuncSetAttribute(edge_mlp_v4,
                         cudaFuncAttributeMaxDynamicSharedMemorySize, SMEM_BYTES);

    const int n_edges = in_sizes[4];
    const int grid = n_edges / CTA_M;   // 3125
    edge_mlp_v4<<<grid, THREADS, SMEM_BYTES>>>(src, dstp, ea, u, bat,
                                               W1, b1, W2, b2, W3, b3, out);
}

// round 5
// speedup vs baseline: 1.1107x; 1.0763x over previous
#include <cuda_runtime.h>
#include <cstdint>

#define THREADS 256
#define CTA_M   64
#define HST     260                       // H row stride (floats)
#define SH_FLOATS (CTA_M * HST)           // 16640
#define SXOFF   SH_FLOATS
#define SXSZ    (CTA_M * 32)              // 2048
#define SWOFF   (SXOFF + SXSZ)            // 18688
#define SWSZ    (32 * 256)                // 8192
#define SMEM_FLOATS (SWOFF + SWSZ)        // 26880
#define SMEM_BYTES  (SMEM_FLOATS * 4)     // 107520  (2 CTAs/SM: 215040 <= 228KB)

// pre-rounded (tf32) weight scratch
__device__ float g_W1r[512 * 256];
__device__ float g_W2r[256 * 256];
__device__ float g_W3r[256 * 128];

__device__ __forceinline__ uint32_t smem_u32(const void* p) {
    uint32_t a;
    asm("{ .reg .u64 t; cvta.to.shared.u64 t, %1; cvt.u32.u64 %0, t; }" : "=r"(a) : "l"(p));
    return a;
}
__device__ __forceinline__ float f2tf32f(float x) {
    uint32_t r; asm("cvt.rna.tf32.f32 %0, %1;" : "=r"(r) : "f"(x));
    return __uint_as_float(r);
}
__device__ __forceinline__ uint32_t tf32_bits(float x) {
    uint32_t r; asm("cvt.rna.tf32.f32 %0, %1;" : "=r"(r) : "f"(x));
    return r;
}
__device__ __forceinline__ float softplus_f(float x) {
    return (x > 20.0f) ? x : __logf(1.0f + __expf(x));
}
__device__ __forceinline__ void mma8(float* c,
                                     uint32_t a0, uint32_t a1, uint32_t a2, uint32_t a3,
                                     uint32_t b0, uint32_t b1) {
    asm volatile(
        "mma.sync.aligned.m16n8k8.row.col.f32.tf32.tf32.f32 "
        "{%0,%1,%2,%3}, {%4,%5,%6,%7}, {%8,%9}, {%0,%1,%2,%3};\n"
        : "+f"(c[0]), "+f"(c[1]), "+f"(c[2]), "+f"(c[3])
        : "r"(a0), "r"(a1), "r"(a2), "r"(a3), "r"(b0), "r"(b1));
}
__device__ __forceinline__ void cp16(uint32_t dst, const void* src) {
    asm volatile("cp.async.cg.shared.global [%0], [%1], 16;" :: "r"(dst), "l"(src) : "memory");
}
#define CP_COMMIT() asm volatile("cp.async.commit_group;" ::: "memory")
#define CP_WAIT0()  asm volatile("cp.async.wait_group 0;" ::: "memory")

// ---- GEMM on one 32-wide K chunk. Warp tile 64M x (NT*8)N, MT=4, m0=0.
// AX: A from X buffer (stride 32, col c -> c ^ (g<<2), raw fp32 -> cvt at read)
// !AX: A from H (stride HST, pre-rounded tf32)
// B from W buffer (stride 256, col n -> n ^ ((k&7)<<3)), pre-rounded tf32.
template <int NT, bool AX>
__device__ __forceinline__ void gemm32(float acc[4][NT][4],
                                       const float* sA, const float* sB,
                                       int n0, int g, int t) {
#pragma unroll
    for (int kk = 0; kk < 32; kk += 8) {
        uint32_t a[4][4];
#pragma unroll
        for (int mt = 0; mt < 4; mt++) {
            int r = mt * 16 + g;
            if (AX) {
                const float* p = sA + r * 32;
                int c0 = (kk + t) ^ (g << 2);
                int c1 = (kk + t + 4) ^ (g << 2);
                a[mt][0] = tf32_bits(p[c0]);
                a[mt][1] = tf32_bits(p[8 * 32 + c0]);
                a[mt][2] = tf32_bits(p[c1]);
                a[mt][3] = tf32_bits(p[8 * 32 + c1]);
            } else {
                const float* p = sA + r * HST + kk + t;
                a[mt][0] = __float_as_uint(p[0]);
                a[mt][1] = __float_as_uint(p[8 * HST]);
                a[mt][2] = __float_as_uint(p[4]);
                a[mt][3] = __float_as_uint(p[8 * HST + 4]);
            }
        }
        const float* pb0 = sB + (kk + t) * 256;
        const float* pb1 = sB + (kk + t + 4) * 256;
        int x0 = t << 3;
        int x1 = (t + 4) << 3;
#pragma unroll
        for (int nt = 0; nt < NT; nt++) {
            int n = n0 + nt * 8 + g;
            uint32_t b0 = __float_as_uint(pb0[n ^ x0]);
            uint32_t b1 = __float_as_uint(pb1[n ^ x1]);
#pragma unroll
            for (int mt = 0; mt < 4; mt++)
                mma8(acc[mt][nt], a[mt][0], a[mt][1], a[mt][2], a[mt][3], b0, b1);
        }
    }
}

// ---- async staging: X chunk kc (32 K-cols of concat) for 64 edges ----
__device__ __forceinline__ void stage_x(uint32_t xbase, int kc, long e0,
                                        const float* __restrict__ src,
                                        const float* __restrict__ dstp,
                                        const float* __restrict__ ea,
                                        const float* __restrict__ u,
                                        const void* __restrict__ batch, int b64, int tid) {
    int k0 = kc * 32, seg = k0 >> 7, off = k0 & 127;
#pragma unroll
    for (int it = 0; it < 2; it++) {
        int task = tid + it * THREADS;       // 64 rows * 8 q = 512 tasks
        int row = task >> 3, q = task & 7;
        const float* p;
        if (seg == 0)      p = src  + (e0 + row) * 128;
        else if (seg == 1) p = dstp + (e0 + row) * 128;
        else if (seg == 2) p = ea   + (e0 + row) * 128;
        else {
            long bi = b64 ? (long)((const long long*)batch)[e0 + row]
                          : (long)((const int*)batch)[e0 + row];
            p = u + bi * 128;
        }
        uint32_t dst = xbase + (row * 32 + ((q * 4) ^ ((row & 7) << 2))) * 4;
        cp16(dst, p + off + q * 4);
    }
}

// ---- async staging: W chunk kc (rows kc*32..+32 of [K][N], pre-rounded) ----
template <int N>
__device__ __forceinline__ void stage_w(uint32_t wbase, const float* __restrict__ Wg,
                                        int kc, int tid) {
    const int F4 = N / 4;
#pragma unroll
    for (int it = 0; it < (32 * F4) / THREADS; it++) {
        int task = tid + it * THREADS;
        int row = task / F4, c4 = task % F4;
        uint32_t dst = wbase + (row * 256 + ((c4 * 4) ^ ((row & 7) << 3))) * 4;
        cp16(dst, Wg + (long)(kc * 32 + row) * N + c4 * 4);
    }
}

// ---- epilogue layers 1/2: bias + softplus + tf32-round -> sH ----
template <int NT>
__device__ __forceinline__ void epi_h(float acc[4][NT][4], float* sH,
                                      const float* __restrict__ bias,
                                      int n0, int g, int t) {
#pragma unroll
    for (int nt = 0; nt < NT; nt++) {
        int c = n0 + nt * 8 + 2 * t;
        float bb0 = __ldg(bias + c);
        float bb1 = __ldg(bias + c + 1);
#pragma unroll
        for (int mt = 0; mt < 4; mt++) {
            int r = mt * 16 + g;
            sH[r * HST + c]           = f2tf32f(softplus_f(acc[mt][nt][0] + bb0));
            sH[r * HST + c + 1]       = f2tf32f(softplus_f(acc[mt][nt][1] + bb1));
            sH[(r + 8) * HST + c]     = f2tf32f(softplus_f(acc[mt][nt][2] + bb0));
            sH[(r + 8) * HST + c + 1] = f2tf32f(softplus_f(acc[mt][nt][3] + bb1));
        }
    }
}

// prepass: tf32-round all weights into __device__ scratch
__global__ void round_weights(const float* __restrict__ W1,
                              const float* __restrict__ W2,
                              const float* __restrict__ W3) {
    int i = blockIdx.x * blockDim.x + threadIdx.x;
    if (i < 512 * 256) g_W1r[i] = f2tf32f(W1[i]);
    if (i < 256 * 256) g_W2r[i] = f2tf32f(W2[i]);
    if (i < 256 * 128) g_W3r[i] = f2tf32f(W3[i]);
}

__global__ void __launch_bounds__(THREADS, 2)
edge_mlp_v5(const float* __restrict__ src, const float* __restrict__ dstp,
            const float* __restrict__ ea, const float* __restrict__ u,
            const void* __restrict__ batch,
            const float* __restrict__ b1, const float* __restrict__ b2,
            const float* __restrict__ b3,
            float* __restrict__ out) {
    extern __shared__ float sm[];
    float* sH = sm;
    float* sX = sm + SXOFF;
    float* sW = sm + SWOFF;
    uint32_t sb = smem_u32(sm);
    uint32_t xb = sb + SXOFF * 4;
    uint32_t wbx = sb + SWOFF * 4;

    int tid = threadIdx.x;
    int wid = tid >> 5;
    int lane = tid & 31;
    int g = lane >> 2;
    int t = lane & 3;
    int n0 = wid * 32;            // layers 1/2: 8 warps over N=256
    int n3 = wid * 16;            // layer 3: N=128
    long e0 = (long)blockIdx.x * CTA_M;

    __shared__ int b64s;
    if (tid == 0) {
        const long long* p = (const long long*)batch;
        int f = 1;
        for (int i = 0; i < 16; i++) { long long v = p[i]; if (v < 0 || v >= 64) f = 0; }
        b64s = f;
    }
    __syncthreads();
    int b64 = b64s;

    float acc[4][4][4];
#pragma unroll
    for (int a = 0; a < 4; a++)
#pragma unroll
        for (int b = 0; b < 4; b++)
#pragma unroll
            for (int c = 0; c < 4; c++) acc[a][b][c] = 0.0f;

    // ================= Layer 1: K=512 (16 chunks), N=256 =================
#pragma unroll 1
    for (int kc = 0; kc < 16; kc++) {
        stage_x(xb, kc, e0, src, dstp, ea, u, batch, b64, tid);
        stage_w<256>(wbx, g_W1r, kc, tid);
        CP_COMMIT();
        CP_WAIT0();
        __syncthreads();
        gemm32<4, true>(acc, sX, sW, n0, g, t);
        __syncthreads();
    }
    epi_h<4>(acc, sH, b1, n0, g, t);

    // ================= Layer 2: K=256 (8 chunks), N=256, A = sH ==========
#pragma unroll
    for (int a = 0; a < 4; a++)
#pragma unroll
        for (int b = 0; b < 4; b++)
#pragma unroll
            for (int c = 0; c < 4; c++) acc[a][b][c] = 0.0f;
#pragma unroll 1
    for (int kc = 0; kc < 8; kc++) {
        stage_w<256>(wbx, g_W2r, kc, tid);
        CP_COMMIT();
        CP_WAIT0();
        __syncthreads();          // first iter also publishes sH
        gemm32<4, false>(acc, sH + kc * 32, sW, n0, g, t);
        __syncthreads();
    }
    epi_h<4>(acc, sH, b2, n0, g, t);

    // ================= Layer 3: K=256 (8 chunks), N=128, A = sH ==========
    float acc3[4][2][4];
#pragma unroll
    for (int a = 0; a < 4; a++)
#pragma unroll
        for (int b = 0; b < 2; b++)
#pragma unroll
            for (int c = 0; c < 4; c++) acc3[a][b][c] = 0.0f;
#pragma unroll 1
    for (int kc = 0; kc < 8; kc++) {
        stage_w<128>(wbx, g_W3r, kc, tid);
        CP_COMMIT();
        CP_WAIT0();
        __syncthreads();
        gemm32<2, false>(acc3, sH + kc * 32, sW, n3, g, t);
        __syncthreads();
    }

    // ---- output epilogue: bias -> sH bounce (cols 0..127) -> coalesced STG
#pragma unroll
    for (int nt = 0; nt < 2; nt++) {
        int c = n3 + nt * 8 + 2 * t;
        float bb0 = __ldg(b3 + c);
        float bb1 = __ldg(b3 + c + 1);
#pragma unroll
        for (int mt = 0; mt < 4; mt++) {
            int r = mt * 16 + g;
            sH[r * HST + c]           = acc3[mt][nt][0] + bb0;
            sH[r * HST + c + 1]       = acc3[mt][nt][1] + bb1;
            sH[(r + 8) * HST + c]     = acc3[mt][nt][2] + bb0;
            sH[(r + 8) * HST + c + 1] = acc3[mt][nt][3] + bb1;
        }
    }
    __syncthreads();
#pragma unroll
    for (int it = 0; it < 8; it++) {
        int task = tid + it * THREADS;      // 64 rows * 32 float4
        int row = task >> 5, c4 = task & 31;
        *(float4*)(out + (e0 + row) * 128 + c4 * 4) =
            *(const float4*)(sH + row * HST + c4 * 4);
    }
}

extern "C" void kernel_launch(void* const* d_in, const int* in_sizes, int n_in,
                              void* d_out, int out_size) {
    const float* src  = (const float*)d_in[0];
    const float* dstp = (const float*)d_in[1];
    const float* ea   = (const float*)d_in[2];
    const float* u    = (const float*)d_in[3];
    const void*  bat  = (const void*)d_in[4];
    const float* W1   = (const float*)d_in[5];
    const float* b1   = (const float*)d_in[6];
    const float* W2   = (const float*)d_in[7];
    const float* b2   = (const float*)d_in[8];
    const float* W3   = (const float*)d_in[9];
    const float* b3   = (const float*)d_in[10];
    float* out = (float*)d_out;

    cudaFuncSetAttribute(edge_mlp_v5,
                         cudaFuncAttributeMaxDynamicSharedMemorySize, SMEM_BYTES);

    round_weights<<<512, 256>>>(W1, W2, W3);

    const int n_edges = in_sizes[4];
    const int grid = n_edges / CTA_M;   // 6250
    edge_mlp_v5<<<grid, THREADS, SMEM_BYTES>>>(src, dstp, ea, u, bat,
                                               b1, b2, b3, out);
}

// round 6
// speedup vs baseline: 1.6073x; 1.4472x over previous
#include <cuda_runtime.h>
#include <cuda_fp16.h>
#include <cstdint>

#define THREADS 256
#define CTA_M   64
// word-unit (4B) shared layout
#define HSTW    132                     // H row stride in words (264 halves)
#define HW      (64 * HSTW)             // 8448 words
#define XOFFW   HW
#define XSTW    20                      // X row stride words (40 halves: 32 + pad)
#define XSLOTW  (64 * XSTW)             // 1280
#define WOFFW   (XOFFW + 2 * XSLOTW)    // 11008
#define WSTW    20                      // W row stride words
#define WSLOTW  (256 * WSTW)            // 5120
#define SMEM_WORDS (WOFFW + 2 * WSLOTW) // 21248
#define SMEM_BYTES (SMEM_WORDS * 4)     // 84992 (2 CTAs/SM: 169984)

// pre-transposed + fp16-converted weights: Wt[n][k]
__device__ __half g_W1t[256 * 512];
__device__ __half g_W2t[256 * 256];
__device__ __half g_W3t[128 * 256];

__device__ __forceinline__ uint32_t smem_u32(const void* p) {
    uint32_t a;
    asm("{ .reg .u64 t; cvta.to.shared.u64 t, %1; cvt.u32.u64 %0, t; }" : "=r"(a) : "l"(p));
    return a;
}
__device__ __forceinline__ float softplus_f(float x) {
    return (x > 20.0f) ? x : __logf(1.0f + __expf(x));
}
__device__ __forceinline__ uint32_t pack_h2(float lo, float hi) {
    __half2 h = __halves2half2(__float2half_rn(lo), __float2half_rn(hi));
    return *(uint32_t*)&h;
}
__device__ __forceinline__ void mma16(float* c, uint32_t a0, uint32_t a1,
                                      uint32_t a2, uint32_t a3,
                                      uint32_t b0, uint32_t b1) {
    asm volatile(
        "mma.sync.aligned.m16n8k16.row.col.f32.f16.f16.f32 "
        "{%0,%1,%2,%3}, {%4,%5,%6,%7}, {%8,%9}, {%0,%1,%2,%3};\n"
        : "+f"(c[0]), "+f"(c[1]), "+f"(c[2]), "+f"(c[3])
        : "r"(a0), "r"(a1), "r"(a2), "r"(a3), "r"(b0), "r"(b1));
}
__device__ __forceinline__ void cp16(uint32_t dst, const void* src) {
    asm volatile("cp.async.cg.shared.global [%0], [%1], 16;" :: "r"(dst), "l"(src) : "memory");
}
#define CP_COMMIT() asm volatile("cp.async.commit_group;" ::: "memory")
#define CP_WAIT1()  asm volatile("cp.async.wait_group 1;" ::: "memory")

// ---- GEMM over one 32-K chunk, fp16 m16n8k16. Warp tile 64M x (NT*8)N.
// sA: word ptr, row stride astrw, halves K-major. sB: Wt slot, stride WSTW.
template <int NT>
__device__ __forceinline__ void gemm16(float acc[4][NT][4],
                                       const uint32_t* sA, int astrw,
                                       const uint32_t* sB,
                                       int n0, int g, int t) {
#pragma unroll
    for (int kkw = 0; kkw < 16; kkw += 8) {   // two K=16 steps
        uint32_t a[4][4];
#pragma unroll
        for (int mt = 0; mt < 4; mt++) {
            const uint32_t* p = sA + (mt * 16 + g) * astrw + t + kkw;
            a[mt][0] = p[0];
            a[mt][1] = p[8 * astrw];
            a[mt][2] = p[4];
            a[mt][3] = p[8 * astrw + 4];
        }
#pragma unroll
        for (int nt = 0; nt < NT; nt++) {
            const uint32_t* pb = sB + (n0 + nt * 8 + g) * WSTW + t + kkw;
            uint32_t b0 = pb[0];
            uint32_t b1 = pb[4];
#pragma unroll
            for (int mt = 0; mt < 4; mt++)
                mma16(acc[mt][nt], a[mt][0], a[mt][1], a[mt][2], a[mt][3], b0, b1);
        }
    }
}

// ---- X staging: LDG float4 -> cvt half -> STS.64 (64 rows x 32 halves) ----
__device__ __forceinline__ void stage_x(uint32_t* smw, int slot, int kc, long e0,
                                        const float* __restrict__ src,
                                        const float* __restrict__ dstp,
                                        const float* __restrict__ ea,
                                        const float* __restrict__ u,
                                        const void* __restrict__ batch, int b64, int tid) {
    uint32_t* x = smw + XOFFW + slot * XSLOTW;
    int k0 = kc * 32, seg = k0 >> 7, off = k0 & 127;
#pragma unroll
    for (int it = 0; it < 2; it++) {
        int task = tid + it * THREADS;      // 512 tasks: 64 rows x 8 quads
        int row = task >> 3, q = task & 7;
        const float* p;
        if (seg == 0)      p = src  + (e0 + row) * 128;
        else if (seg == 1) p = dstp + (e0 + row) * 128;
        else if (seg == 2) p = ea   + (e0 + row) * 128;
        else {
            long bi = b64 ? (long)((const long long*)batch)[e0 + row]
                          : (long)((const int*)batch)[e0 + row];
            p = u + bi * 128;
        }
        float4 v = *(const float4*)(p + off + q * 4);
        uint2 o;
        o.x = pack_h2(v.x, v.y);
        o.y = pack_h2(v.z, v.w);
        *(uint2*)(x + row * XSTW + q * 2) = o;
    }
}

// ---- W staging via cp.async from pre-transposed half weights ----
template <int NROWS, int KFULL>
__device__ __forceinline__ void stage_w(uint32_t wbase_byte, const __half* __restrict__ Wt,
                                        int kc, int tid) {
#pragma unroll
    for (int it = 0; it < (NROWS * 4) / THREADS; it++) {
        int task = tid + it * THREADS;
        int row = task >> 2, c8 = task & 3;          // 4x cp16 per 32-half row
        uint32_t dst = wbase_byte + (row * WSTW + c8 * 4) * 4;
        cp16(dst, Wt + (long)row * KFULL + kc * 32 + c8 * 8);
    }
}

// ---- epilogue layers 1/2: bias + softplus -> half2 into H ----
template <int NT>
__device__ __forceinline__ void epi_h(float acc[4][NT][4], uint32_t* smw,
                                      const float* __restrict__ bias,
                                      int n0, int g, int t) {
#pragma unroll
    for (int nt = 0; nt < NT; nt++) {
        int c = n0 + nt * 8 + 2 * t;
        float bb0 = __ldg(bias + c);
        float bb1 = __ldg(bias + c + 1);
#pragma unroll
        for (int mt = 0; mt < 4; mt++) {
            int r = mt * 16 + g;
            smw[r * HSTW + (c >> 1)] =
                pack_h2(softplus_f(acc[mt][nt][0] + bb0), softplus_f(acc[mt][nt][1] + bb1));
            smw[(r + 8) * HSTW + (c >> 1)] =
                pack_h2(softplus_f(acc[mt][nt][2] + bb0), softplus_f(acc[mt][nt][3] + bb1));
        }
    }
}

// ---- prepass: transpose W [K][N] -> Wt [N][K] + cvt fp16 ----
__global__ void prep_w(const float* __restrict__ W, __half* __restrict__ Wt,
                       int K, int N) {
    __shared__ float tile[32][33];
    int kb = blockIdx.x * 32, nb = blockIdx.y * 32;
    int tx = threadIdx.x, ty = threadIdx.y;
    for (int i = ty; i < 32; i += 8)
        tile[i][tx] = W[(long)(kb + i) * N + nb + tx];
    __syncthreads();
    for (int i = ty; i < 32; i += 8)
        Wt[(long)(nb + i) * K + kb + tx] = __float2half_rn(tile[tx][i]);
}

__global__ void __launch_bounds__(THREADS, 2)
edge_mlp_v6(const float* __restrict__ src, const float* __restrict__ dstp,
            const float* __restrict__ ea, const float* __restrict__ u,
            const void* __restrict__ batch,
            const float* __restrict__ b1, const float* __restrict__ b2,
            const float* __restrict__ b3,
            float* __restrict__ out) {
    extern __shared__ uint32_t smw[];
    uint32_t sb = smem_u32(smw);
    uint32_t wbb[2] = { sb + WOFFW * 4, sb + (WOFFW + WSLOTW) * 4 };

    int tid = threadIdx.x;
    int wid = tid >> 5;
    int lane = tid & 31;
    int g = lane >> 2;
    int t = lane & 3;
    int n0 = wid * 32;            // layers 1/2: 8 warps x 32N
    int n3 = wid * 16;            // layer 3: 8 warps x 16N
    long e0 = (long)blockIdx.x * CTA_M;

    __shared__ int b64s;
    if (tid == 0) {
        const long long* p = (const long long*)batch;
        int f = 1;
        for (int i = 0; i < 16; i++) { long long v = p[i]; if (v < 0 || v >= 64) f = 0; }
        b64s = f;
    }
    __syncthreads();
    int b64 = b64s;

    float acc[4][4][4];
#pragma unroll
    for (int a = 0; a < 4; a++)
#pragma unroll
        for (int b = 0; b < 4; b++)
#pragma unroll
            for (int c = 0; c < 4; c++) acc[a][b][c] = 0.0f;

    // ================= Layer 1: K=512 (16 chunks), N=256 =================
    stage_x(smw, 0, 0, e0, src, dstp, ea, u, batch, b64, tid);
    stage_w<256, 512>(wbb[0], g_W1t, 0, tid);
    CP_COMMIT();
    stage_x(smw, 1, 1, e0, src, dstp, ea, u, batch, b64, tid);
    stage_w<256, 512>(wbb[1], g_W1t, 1, tid);
    CP_COMMIT();
#pragma unroll 1
    for (int kc = 0; kc < 16; kc++) {
        int s = kc & 1;
        CP_WAIT1();
        __syncthreads();
        gemm16<4>(acc, smw + XOFFW + s * XSLOTW, XSTW, smw + WOFFW + s * WSLOTW, n0, g, t);
        __syncthreads();
        if (kc < 14) {
            stage_x(smw, s, kc + 2, e0, src, dstp, ea, u, batch, b64, tid);
            stage_w<256, 512>(wbb[s], g_W1t, kc + 2, tid);
        }
        CP_COMMIT();
    }

    // ================= Layer 2: K=256 (8 chunks), N=256, A = H ==========
    stage_w<256, 256>(wbb[0], g_W2t, 0, tid); CP_COMMIT();
    stage_w<256, 256>(wbb[1], g_W2t, 1, tid); CP_COMMIT();
    epi_h<4>(acc, smw, b1, n0, g, t);
#pragma unroll
    for (int a = 0; a < 4; a++)
#pragma unroll
        for (int b = 0; b < 4; b++)
#pragma unroll
            for (int c = 0; c < 4; c++) acc[a][b][c] = 0.0f;
#pragma unroll 1
    for (int kc = 0; kc < 8; kc++) {
        int s = kc & 1;
        CP_WAIT1();
        __syncthreads();           // first iter also publishes H
        gemm16<4>(acc, smw + kc * 16, HSTW, smw + WOFFW + s * WSLOTW, n0, g, t);
        __syncthreads();
        if (kc < 6) stage_w<256, 256>(wbb[s], g_W2t, kc + 2, tid);
        CP_COMMIT();
    }

    // ================= Layer 3: K=256 (8 chunks), N=128, A = H ==========
    stage_w<128, 256>(wbb[0], g_W3t, 0, tid); CP_COMMIT();
    stage_w<128, 256>(wbb[1], g_W3t, 1, tid); CP_COMMIT();
    epi_h<4>(acc, smw, b2, n0, g, t);
    float acc3[4][2][4];
#pragma unroll
    for (int a = 0; a < 4; a++)
#pragma unroll
        for (int b = 0; b < 2; b++)
#pragma unroll
            for (int c = 0; c < 4; c++) acc3[a][b][c] = 0.0f;
#pragma unroll 1
    for (int kc = 0; kc < 8; kc++) {
        int s = kc & 1;
        CP_WAIT1();
        __syncthreads();
        gemm16<2>(acc3, smw + kc * 16, HSTW, smw + WOFFW + s * WSLOTW, n3, g, t);
        __syncthreads();
        if (kc < 6) stage_w<128, 256>(wbb[s], g_W3t, kc + 2, tid);
        CP_COMMIT();
    }

    // ---- output epilogue: f32 scratch over H region -> coalesced STG ----
    float* fH = (float*)smw;
#pragma unroll
    for (int nt = 0; nt < 2; nt++) {
        int c = n3 + nt * 8 + 2 * t;
        float bb0 = __ldg(b3 + c);
        float bb1 = __ldg(b3 + c + 1);
#pragma unroll
        for (int mt = 0; mt < 4; mt++) {
            int r = mt * 16 + g;
            *(float2*)(fH + r * HSTW + c) =
                make_float2(acc3[mt][nt][0] + bb0, acc3[mt][nt][1] + bb1);
            *(float2*)(fH + (r + 8) * HSTW + c) =
                make_float2(acc3[mt][nt][2] + bb0, acc3[mt][nt][3] + bb1);
        }
    }
    __syncthreads();
#pragma unroll
    for (int it = 0; it < 8; it++) {
        int task = tid + it * THREADS;      // 64 rows x 32 float4
        int row = task >> 5, c4 = task & 31;
        *(float4*)(out + (e0 + row) * 128 + c4 * 4) =
            *(const float4*)(fH + row * HSTW + c4 * 4);
    }
}

extern "C" void kernel_launch(void* const* d_in, const int* in_sizes, int n_in,
                              void* d_out, int out_size) {
    const float* src  = (const float*)d_in[0];
    const float* dstp = (const float*)d_in[1];
    const float* ea   = (const float*)d_in[2];
    const float* u    = (const float*)d_in[3];
    const void*  bat  = (const void*)d_in[4];
    const float* W1   = (const float*)d_in[5];
    const float* b1   = (const float*)d_in[6];
    const float* W2   = (const float*)d_in[7];
    const float* b2   = (const float*)d_in[8];
    const float* W3   = (const float*)d_in[9];
    const float* b3   = (const float*)d_in[10];
    float* out = (float*)d_out;

    cudaFuncSetAttribute(edge_mlp_v6,
                         cudaFuncAttributeMaxDynamicSharedMemorySize, SMEM_BYTES);

    __half *w1t, *w2t, *w3t;
    cudaGetSymbolAddress((void**)&w1t, g_W1t);
    cudaGetSymbolAddress((void**)&w2t, g_W2t);
    cudaGetSymbolAddress((void**)&w3t, g_W3t);
    dim3 blk(32, 8);
    prep_w<<<dim3(16, 8), blk>>>(W1, w1t, 512, 256);
    prep_w<<<dim3(8, 8),  blk>>>(W2, w2t, 256, 256);
    prep_w<<<dim3(8, 4),  blk>>>(W3, w3t, 256, 128);

    const int n_edges = in_sizes[4];
    const int grid = n_edges / CTA_M;   // 6250
    edge_mlp_v6<<<grid, THREADS, SMEM_BYTES>>>(src, dstp, ea, u, bat,
                                               b1, b2, b3, out);
}

// round 7
// speedup vs baseline: 1.9233x; 1.1966x over previous
#include <cuda_runtime.h>
#include <cuda_fp16.h>
#include <cstdint>

#define THREADS 256
#define CTA_M   64
// word (4B) layout. H: 64 rows x 128 words (256 halves), swizzled, at offset 0.
// X double-buffer aliases the H region (X dead before H is written).
// W slots: 256 rows x 32 words, swizzled.
#define HROW    128
#define XSLOTW  2048                    // 64 rows x 32 words
#define WOFFW   8192
#define WSLOTW  8192                    // 256 rows x 32 words
#define SMEM_WORDS (WOFFW + 2 * WSLOTW) // 24576
#define SMEM_BYTES (SMEM_WORDS * 4)     // 98304 (2 CTAs/SM: 196608 <= 228KB)

// pre-transposed, fp16, pair-interleaved weights: Wt[n][phys(k)]
__device__ __half g_W1t[256 * 512];
__device__ __half g_W2t[256 * 256];
__device__ __half g_W3t[128 * 256];

__device__ __forceinline__ uint32_t smem_u32(const void* p) {
    uint32_t a;
    asm("{ .reg .u64 t; cvta.to.shared.u64 t, %1; cvt.u32.u64 %0, t; }" : "=r"(a) : "l"(p));
    return a;
}
__device__ __forceinline__ float softplus_f(float x) {
    return (x > 20.0f) ? x : __logf(1.0f + __expf(x));
}
__device__ __forceinline__ uint32_t pack_h2(float lo, float hi) {
    __half2 h = __halves2half2(__float2half_rn(lo), __float2half_rn(hi));
    return *(uint32_t*)&h;
}
__device__ __forceinline__ void mma16(float* c, uint32_t a0, uint32_t a1,
                                      uint32_t a2, uint32_t a3,
                                      uint32_t b0, uint32_t b1) {
    asm volatile(
        "mma.sync.aligned.m16n8k16.row.col.f32.f16.f16.f32 "
        "{%0,%1,%2,%3}, {%4,%5,%6,%7}, {%8,%9}, {%0,%1,%2,%3};\n"
        : "+f"(c[0]), "+f"(c[1]), "+f"(c[2]), "+f"(c[3])
        : "r"(a0), "r"(a1), "r"(a2), "r"(a3), "r"(b0), "r"(b1));
}
__device__ __forceinline__ void cp16(uint32_t dst, const void* src) {
    asm volatile("cp.async.cg.shared.global [%0], [%1], 16;" :: "r"(dst), "l"(src) : "memory");
}
#define CP_COMMIT() asm volatile("cp.async.commit_group;" ::: "memory")
#define CP_WAIT1()  asm volatile("cp.async.wait_group 1;" ::: "memory")

// physical half index for pair-interleaved k16 groups:
// word w -> (w & ~7) | ((w&3)<<1) | ((w>>2)&1)
__host__ __device__ __forceinline__ int phys_k(int k) {
    int w = k >> 1;
    int pw = (w & ~7) | (((w & 3) << 1) | ((w >> 2) & 1));
    return (pw << 1) | (k & 1);
}

// ---- GEMM over one 64-K chunk, fp16 m16n8k16. Warp tile 64M x (NT*8)N.
// sA: word ptr at chunk base, row stride astrw, pair-interleaved + swizzled.
// sB: W slot (stride 32 words), same layout.
template <int NT>
__device__ __forceinline__ void gemm64(float acc[4][NT][4],
                                       const uint32_t* sA, int astrw,
                                       const uint32_t* sB,
                                       int n0, int g, int t) {
    int xo = (g & 3) << 3;   // row&3 == g&3 for all rows we touch
#pragma unroll
    for (int gi = 0; gi < 4; gi++) {             // four k16 steps
        int off = (gi * 8 + 2 * t) ^ xo;
        uint32_t a[4][4];
#pragma unroll
        for (int mt = 0; mt < 4; mt++) {
            int r = mt * 16 + g;
            uint2 p0 = *(const uint2*)(sA + r * astrw + off);
            uint2 p1 = *(const uint2*)(sA + (r + 8) * astrw + off);
            a[mt][0] = p0.x; a[mt][2] = p0.y;
            a[mt][1] = p1.x; a[mt][3] = p1.y;
        }
#pragma unroll
        for (int nt = 0; nt < NT; nt++) {
            uint2 bb = *(const uint2*)(sB + (n0 + nt * 8 + g) * 32 + off);
#pragma unroll
            for (int mt = 0; mt < 4; mt++)
                mma16(acc[mt][nt], a[mt][0], a[mt][1], a[mt][2], a[mt][3], bb.x, bb.y);
        }
    }
}

// ---- X staging: one 64-K chunk for 64 edges. 1 task/thread:
// row = tid>>2, grp = tid&3 (k16 group). 4 LDG.128 -> 2 STS.128 interleaved.
__device__ __forceinline__ void stage_x(uint32_t* smw, int slot, int kc, long e0,
                                        const float* __restrict__ src,
                                        const float* __restrict__ dstp,
                                        const float* __restrict__ ea,
                                        const float* __restrict__ u,
                                        const void* __restrict__ batch, int b64, int tid) {
    uint32_t* x = smw + slot * XSLOTW;
    int row = tid >> 2, grp = tid & 3;
    int k0 = kc * 64, seg = k0 >> 7, off = (k0 & 127) + grp * 16;
    const float* p;
    if (seg == 0)      p = src  + (e0 + row) * 128;
    else if (seg == 1) p = dstp + (e0 + row) * 128;
    else if (seg == 2) p = ea   + (e0 + row) * 128;
    else {
        long bi = b64 ? (long)((const long long*)batch)[e0 + row]
                      : (long)((const int*)batch)[e0 + row];
        p = u + bi * 128;
    }
    float4 va = *(const float4*)(p + off);
    float4 vb = *(const float4*)(p + off + 8);
    float4 vc = *(const float4*)(p + off + 4);
    float4 vd = *(const float4*)(p + off + 12);
    int xo = (row & 3) << 3;
    uint4 o1 = make_uint4(pack_h2(va.x, va.y), pack_h2(vb.x, vb.y),
                          pack_h2(va.z, va.w), pack_h2(vb.z, vb.w));
    uint4 o2 = make_uint4(pack_h2(vc.x, vc.y), pack_h2(vd.x, vd.y),
                          pack_h2(vc.z, vc.w), pack_h2(vd.z, vd.w));
    *(uint4*)(x + row * 32 + ((grp * 8 + 0) ^ xo)) = o1;
    *(uint4*)(x + row * 32 + ((grp * 8 + 4) ^ xo)) = o2;
}

// ---- W staging: 64-K chunk (32 words/row) via cp.async, swizzled dst ----
template <int NROWS, int KFULL>
__device__ __forceinline__ void stage_w(uint32_t wbase_byte, const __half* __restrict__ Wt,
                                        int kc, int tid) {
#pragma unroll
    for (int it = 0; it < (NROWS * 8) / THREADS; it++) {
        int task = tid + it * THREADS;
        int row = task >> 3, cw = task & 7;
        uint32_t dst = wbase_byte + (row * 32 + ((cw * 4) ^ ((row & 3) << 3))) * 4;
        cp16(dst, Wt + (long)row * KFULL + kc * 64 + cw * 8);
    }
}

// ---- epilogue layers 1/2: bias + softplus -> half2 into H (interleaved+swizzled)
template <int NT>
__device__ __forceinline__ void epi_h(float acc[4][NT][4], uint32_t* smw,
                                      const float* __restrict__ bias,
                                      int n0, int g, int t) {
#pragma unroll
    for (int nt = 0; nt < NT; nt++) {
        int c = n0 + nt * 8 + 2 * t;
        float bb0 = __ldg(bias + c);
        float bb1 = __ldg(bias + c + 1);
        // logical word lw = c>>1; phys within its 8-word group:
        int g8 = (c >> 1) >> 3;
        int pw = (g8 << 3) + 2 * t + (nt & 1);
#pragma unroll
        for (int mt = 0; mt < 4; mt++) {
            int r = mt * 16 + g;
            smw[r * HROW + (pw ^ ((r & 3) << 3))] =
                pack_h2(softplus_f(acc[mt][nt][0] + bb0), softplus_f(acc[mt][nt][1] + bb1));
            smw[(r + 8) * HROW + (pw ^ ((r & 3) << 3))] =
                pack_h2(softplus_f(acc[mt][nt][2] + bb0), softplus_f(acc[mt][nt][3] + bb1));
        }
    }
}

// ---- prepass: W [K][N] -> Wt [N][phys(K)] fp16 ----
__global__ void prep_w(const float* __restrict__ W, __half* __restrict__ Wt,
                       int K, int N) {
    __shared__ float tile[32][33];
    int kb = blockIdx.x * 32, nb = blockIdx.y * 32;
    int tx = threadIdx.x, ty = threadIdx.y;
    for (int i = ty; i < 32; i += 8)
        tile[i][tx] = W[(long)(kb + i) * N + nb + tx];
    __syncthreads();
    for (int i = ty; i < 32; i += 8)
        Wt[(long)(nb + i) * K + phys_k(kb + tx)] = __float2half_rn(tile[tx][i]);
}

__global__ void __launch_bounds__(THREADS, 2)
edge_mlp_v7(const float* __restrict__ src, const float* __restrict__ dstp,
            const float* __restrict__ ea, const float* __restrict__ u,
            const void* __restrict__ batch,
            const float* __restrict__ b1, const float* __restrict__ b2,
            const float* __restrict__ b3,
            float* __restrict__ out) {
    extern __shared__ uint32_t smw[];
    uint32_t sb = smem_u32(smw);
    uint32_t wbb[2] = { sb + WOFFW * 4, sb + (WOFFW + WSLOTW) * 4 };

    int tid = threadIdx.x;
    int wid = tid >> 5;
    int lane = tid & 31;
    int g = lane >> 2;
    int t = lane & 3;
    int n0 = wid * 32;            // layers 1/2: 8 warps x 32N
    int n3 = wid * 16;            // layer 3
    long e0 = (long)blockIdx.x * CTA_M;

    __shared__ int b64s;
    if (tid == 0) {
        const long long* p = (const long long*)batch;
        int f = 1;
        for (int i = 0; i < 16; i++) { long long v = p[i]; if (v < 0 || v >= 64) f = 0; }
        b64s = f;
    }
    __syncthreads();
    int b64 = b64s;

    float acc[4][4][4];
#pragma unroll
    for (int a = 0; a < 4; a++)
#pragma unroll
        for (int b = 0; b < 4; b++)
#pragma unroll
            for (int c = 0; c < 4; c++) acc[a][b][c] = 0.0f;

    // ================= Layer 1: K=512 (8 chunks of 64), N=256 ============
    stage_x(smw, 0, 0, e0, src, dstp, ea, u, batch, b64, tid);
    stage_w<256, 512>(wbb[0], g_W1t, 0, tid);
    CP_COMMIT();
    stage_x(smw, 1, 1, e0, src, dstp, ea, u, batch, b64, tid);
    stage_w<256, 512>(wbb[1], g_W1t, 1, tid);
    CP_COMMIT();
#pragma unroll 1
    for (int kc = 0; kc < 8; kc++) {
        int s = kc & 1;
        CP_WAIT1();
        __syncthreads();
        gemm64<4>(acc, smw + s * XSLOTW, 32, smw + WOFFW + s * WSLOTW, n0, g, t);
        __syncthreads();
        if (kc < 6) {
            stage_x(smw, s, kc + 2, e0, src, dstp, ea, u, batch, b64, tid);
            stage_w<256, 512>(wbb[s], g_W1t, kc + 2, tid);
        }
        CP_COMMIT();
    }

    // ================= Layer 2: K=256 (4 chunks), N=256, A = H ==========
    stage_w<256, 256>(wbb[0], g_W2t, 0, tid); CP_COMMIT();
    stage_w<256, 256>(wbb[1], g_W2t, 1, tid); CP_COMMIT();
    epi_h<4>(acc, smw, b1, n0, g, t);
#pragma unroll
    for (int a = 0; a < 4; a++)
#pragma unroll
        for (int b = 0; b < 4; b++)
#pragma unroll
            for (int c = 0; c < 4; c++) acc[a][b][c] = 0.0f;
#pragma unroll 1
    for (int kc = 0; kc < 4; kc++) {
        int s = kc & 1;
        CP_WAIT1();
        __syncthreads();           // first iter also publishes H
        gemm64<4>(acc, smw + kc * 32, HROW, smw + WOFFW + s * WSLOTW, n0, g, t);
        __syncthreads();
        if (kc < 2) stage_w<256, 256>(wbb[s], g_W2t, kc + 2, tid);
        CP_COMMIT();
    }

    // ================= Layer 3: K=256 (4 chunks), N=128, A = H ==========
    stage_w<128, 256>(wbb[0], g_W3t, 0, tid); CP_COMMIT();
    stage_w<128, 256>(wbb[1], g_W3t, 1, tid); CP_COMMIT();
    epi_h<4>(acc, smw, b2, n0, g, t);
    float acc3[4][2][4];
#pragma unroll
    for (int a = 0; a < 4; a++)
#pragma unroll
        for (int b = 0; b < 2; b++)
#pragma unroll
            for (int c = 0; c < 4; c++) acc3[a][b][c] = 0.0f;
#pragma unroll 1
    for (int kc = 0; kc < 4; kc++) {
        int s = kc & 1;
        CP_WAIT1();
        __syncthreads();
        gemm64<2>(acc3, smw + kc * 32, HROW, smw + WOFFW + s * WSLOTW, n3, g, t);
        __syncthreads();
        if (kc < 2) stage_w<128, 256>(wbb[s], g_W3t, kc + 2, tid);
        CP_COMMIT();
    }

    // ---- output epilogue: f32 scratch (stride 132, spills into dead W) ----
    float* fH = (float*)smw;
#pragma unroll
    for (int nt = 0; nt < 2; nt++) {
        int c = n3 + nt * 8 + 2 * t;
        float bb0 = __ldg(b3 + c);
        float bb1 = __ldg(b3 + c + 1);
#pragma unroll
        for (int mt = 0; mt < 4; mt++) {
            int r = mt * 16 + g;
            *(float2*)(fH + r * 132 + c) =
                make_float2(acc3[mt][nt][0] + bb0, acc3[mt][nt][1] + bb1);
            *(float2*)(fH + (r + 8) * 132 + c) =
                make_float2(acc3[mt][nt][2] + bb0, acc3[mt][nt][3] + bb1);
        }
    }
    __syncthreads();
#pragma unroll
    for (int it = 0; it < 8; it++) {
        int task = tid + it * THREADS;      // 64 rows x 32 float4
        int row = task >> 5, c4 = task & 31;
        *(float4*)(out + (e0 + row) * 128 + c4 * 4) =
            *(const float4*)(fH + row * 132 + c4 * 4);
    }
}

extern "C" void kernel_launch(void* const* d_in, const int* in_sizes, int n_in,
                              void* d_out, int out_size) {
    const float* src  = (const float*)d_in[0];
    const float* dstp = (const float*)d_in[1];
    const float* ea   = (const float*)d_in[2];
    const float* u    = (const float*)d_in[3];
    const void*  bat  = (const void*)d_in[4];
    const float* W1   = (const float*)d_in[5];
    const float* b1   = (const float*)d_in[6];
    const float* W2   = (const float*)d_in[7];
    const float* b2   = (const float*)d_in[8];
    const float* W3   = (const float*)d_in[9];
    const float* b3   = (const float*)d_in[10];
    float* out = (float*)d_out;

    cudaFuncSetAttribute(edge_mlp_v7,
                         cudaFuncAttributeMaxDynamicSharedMemorySize, SMEM_BYTES);

    __half *w1t, *w2t, *w3t;
    cudaGetSymbolAddress((void**)&w1t, g_W1t);
    cudaGetSymbolAddress((void**)&w2t, g_W2t);
    cudaGetSymbolAddress((void**)&w3t, g_W3t);
    dim3 blk(32, 8);
    prep_w<<<dim3(16, 8), blk>>>(W1, w1t, 512, 256);
    prep_w<<<dim3(8, 8),  blk>>>(W2, w2t, 256, 256);
    prep_w<<<dim3(8, 4),  blk>>>(W3, w3t, 256, 128);

    const int n_edges = in_sizes[4];
    const int grid = n_edges / CTA_M;   // 6250
    edge_mlp_v7<<<grid, THREADS, SMEM_BYTES>>>(src, dstp, ea, u, bat,
                                               b1, b2, b3, out);
}